// round 13
// baseline (speedup 1.0000x reference)
#include <cuda_runtime.h>

// B=32, L=1024, D=64.
// Algebraic collapse (verified R1-R12, rel_err ~1.4e-7):
//   out[b,0,:] = sum_l x[b,l,:] / 1024 ;  out[b,1:,:] = 0.
//   W1,b1,W2,b2,timestamp are dead inputs.
//
// R13: two graph nodes.
//   node 1: cudaMemsetAsync(out, 0, 8MB)  -- driver-optimized fill, zeroes
//           everything including row 0.
//   node 2: read-only reduction kernel, 128 blocks x 1024 threads. Block =
//           (batch b, 128B column half h, row-half r): reads 64KB (512 rows
//           x 128B), reduces to 32 floats, atomicAdd into out[b,0,h*32..].
//           Row 0 is pre-zeroed by the memset (stream-ordered before us),
//           so two blocks per slice accumulate safely.

#define NBLOCKS  128
#define NTHREADS 1024

#define FLOATS_PER_BATCH 65536u   // 1024 rows * 64
#define F4_PER_BATCH     16384u
#define F4_PER_ROW       16u

__device__ __forceinline__ void f4add(float4& a, const float4& b) {
    a.x += b.x; a.y += b.y; a.z += b.z; a.w += b.w;
}

__device__ __forceinline__ float4 f4shfl_down(float4 v, int delta) {
    v.x = __shfl_down_sync(0xffffffffu, v.x, delta);
    v.y = __shfl_down_sync(0xffffffffu, v.y, delta);
    v.z = __shfl_down_sync(0xffffffffu, v.z, delta);
    v.w = __shfl_down_sync(0xffffffffu, v.w, delta);
    return v;
}

__global__ void __launch_bounds__(NTHREADS, 1) um_reduce_kernel(
    const float4* __restrict__ x4, float* __restrict__ out)
{
    // block = (b, h, r): bid = ((b*2)+h)*2 + r
    const int bid = blockIdx.x;
    const int r   = bid & 1;         // row half: rows [r*512, r*512+512)
    const int h   = (bid >> 1) & 1;  // 128B column half
    const int b   = bid >> 2;        // batch

    const int tid  = threadIdx.x;
    const int c    = tid & 7;        // float4 column within 128B slice
    const int lg   = tid >> 3;       // 0..127: row group within the half

    const float4* base = x4 + (size_t)b * F4_PER_BATCH
                            + (size_t)(r * 512 + lg) * F4_PER_ROW + h * 8 + c;

    // 4 independent LDG.128, rows lg + {0,128,256,384} within the half
    float4 v0 = base[0];
    float4 v1 = base[(size_t)128 * F4_PER_ROW];
    float4 v2 = base[(size_t)256 * F4_PER_ROW];
    float4 v3 = base[(size_t)384 * F4_PER_ROW];
    f4add(v0, v1); f4add(v2, v3); f4add(v0, v2);

    // warp reduce: lanes sharing (lane & 7) share a column
    f4add(v0, f4shfl_down(v0, 16));
    f4add(v0, f4shfl_down(v0, 8));

    __shared__ float4 sm[32][8];     // [warp][col]
    const int lane = tid & 31;
    const int wid  = tid >> 5;
    if (lane < 8) sm[wid][lane] = v0;
    __syncthreads();

    // single-warp final reduce: lane = (g, cc), g = lane>>3 owns 8 warps
    if (wid == 0) {
        const int cc = lane & 7;
        const int g  = lane >> 3;
        float4 u0 = sm[g*8+0][cc], u1 = sm[g*8+1][cc];
        float4 u2 = sm[g*8+2][cc], u3 = sm[g*8+3][cc];
        float4 u4 = sm[g*8+4][cc], u5 = sm[g*8+5][cc];
        float4 u6 = sm[g*8+6][cc], u7 = sm[g*8+7][cc];
        f4add(u0, u1); f4add(u2, u3); f4add(u4, u5); f4add(u6, u7);
        f4add(u0, u2); f4add(u4, u6); f4add(u0, u4);

        f4add(u0, f4shfl_down(u0, 16));
        f4add(u0, f4shfl_down(u0, 8));

        if (lane < 8) {
            const float inv = 1.0f / 1024.0f;
            float* dst = out + (size_t)b * FLOATS_PER_BATCH + h * 32 + lane * 4;
            atomicAdd(dst + 0, u0.x * inv);
            atomicAdd(dst + 1, u0.y * inv);
            atomicAdd(dst + 2, u0.z * inv);
            atomicAdd(dst + 3, u0.w * inv);
        }
    }
}

extern "C" void kernel_launch(void* const* d_in, const int* in_sizes, int n_in,
                              void* d_out, int out_size) {
    const float4* x4 = (const float4*)d_in[0];   // user_embedding [32,1024,64]
    float* out = (float*)d_out;                  // [32,1024,64]

    // node 1: zero the whole output (driver-optimized fill, graph-capturable)
    cudaMemsetAsync(d_out, 0, (size_t)out_size * sizeof(float));

    // node 2: read + reduce + accumulate into row 0 (ordered after memset)
    um_reduce_kernel<<<NBLOCKS, NTHREADS>>>(x4, out);
}

// round 14
// speedup vs baseline: 1.2605x; 1.2605x over previous
#include <cuda_runtime.h>

// B=32, L=1024, D=64.
// Algebraic collapse (verified R1-R13, rel_err ~1.4e-7):
//   out[b,0,:] = sum_l x[b,l,:] / 1024 ;  out[b,1:,:] = 0.
//   W1,b1,W2,b2,timestamp are dead inputs.
//
// R14 = R6 structure (single kernel, grid 148 x 1024, 1 CTA/SM) with the
// store stream folded into the read blocks' load-latency window:
//   bids [0,64):   READ blocks (batch b, 128B half h). Issue 8 batched
//                  LDG.128, then 4 fire-and-forget STG.128 zeros (batches
//                  0..15, rows 1+) while loads are in flight, then reduce
//                  and exclusively write out[b,0,h*32 : h*32+32).
//   bids [64,148): STORE blocks: zero batches 16..31 rows 1+ (~3 STG/thread).
// All write sets disjoint; no atomics, no fences.

#define RED_BLOCKS   64
#define TOTAL_BLOCKS 148
#define ZERO_BLOCKS  (TOTAL_BLOCKS - RED_BLOCKS)
#define NTHREADS     1024

#define F4_PER_BATCH 16384u   // 1024 rows * 16 float4
#define F4_PER_ROW   16u
#define N_F4_TOTAL   (32u * F4_PER_BATCH)      // 524288
#define F4_SPLIT     (16u * F4_PER_BATCH)      // 262144: batches 0..15

__device__ __forceinline__ void f4add(float4& a, const float4& b) {
    a.x += b.x; a.y += b.y; a.z += b.z; a.w += b.w;
}

__device__ __forceinline__ float4 f4shfl_down(float4 v, int delta) {
    v.x = __shfl_down_sync(0xffffffffu, v.x, delta);
    v.y = __shfl_down_sync(0xffffffffu, v.y, delta);
    v.z = __shfl_down_sync(0xffffffffu, v.z, delta);
    v.w = __shfl_down_sync(0xffffffffu, v.w, delta);
    return v;
}

__global__ void __launch_bounds__(NTHREADS, 1) um_fused_kernel(
    const float4* __restrict__ x4, float4* __restrict__ out4)
{
    const int bid = blockIdx.x;
    const int tid = threadIdx.x;
    const float4 z = make_float4(0.f, 0.f, 0.f, 0.f);

    if (bid < RED_BLOCKS) {
        // ---- READ block: (b, h) owns the 128B slice h of row 0 -----------
        const int b  = bid >> 1;
        const int h  = bid & 1;
        const int c  = tid & 7;        // float4 column within 128B slice
        const int lg = tid >> 3;       // 0..127: row group

        const float4* base = x4 + (size_t)b * F4_PER_BATCH
                                + (size_t)lg * F4_PER_ROW + h * 8 + c;

        // 8 independent LDG.128 from one base + immediate offsets (MLP=8)
        float4 v[8];
        #pragma unroll
        for (int j = 0; j < 8; ++j)
            v[j] = base[(size_t)j * 128u * F4_PER_ROW];   // +128 rows each

        // while loads are in flight: 4 fire-and-forget zero stores
        // (batches 0..15, skipping each batch's row 0)
        {
            const unsigned gt = (unsigned)bid * NTHREADS + (unsigned)tid; // 0..65535
            #pragma unroll
            for (unsigned k = 0; k < 4; ++k) {
                unsigned i = gt + k * 65536u;   // < F4_SPLIT
                if ((i & (F4_PER_BATCH - 1u)) >= F4_PER_ROW)
                    out4[i] = z;
            }
        }

        float4 a0 = v[0], a1 = v[1], a2 = v[2], a3 = v[3];
        f4add(a0, v[4]); f4add(a1, v[5]); f4add(a2, v[6]); f4add(a3, v[7]);
        f4add(a0, a1); f4add(a2, a3); f4add(a0, a2);

        // warp reduce: lanes sharing (lane & 7) share a column
        f4add(a0, f4shfl_down(a0, 16));
        f4add(a0, f4shfl_down(a0, 8));

        __shared__ float4 sm[32][8];   // [warp][col]
        const int lane = tid & 31;
        const int wid  = tid >> 5;
        if (lane < 8) sm[wid][lane] = a0;
        __syncthreads();

        // single-warp batched final reduce
        if (wid == 0) {
            const int cc = lane & 7;
            const int g  = lane >> 3;
            float4 u0 = sm[g*8+0][cc], u1 = sm[g*8+1][cc];
            float4 u2 = sm[g*8+2][cc], u3 = sm[g*8+3][cc];
            float4 u4 = sm[g*8+4][cc], u5 = sm[g*8+5][cc];
            float4 u6 = sm[g*8+6][cc], u7 = sm[g*8+7][cc];
            f4add(u0, u1); f4add(u2, u3); f4add(u4, u5); f4add(u6, u7);
            f4add(u0, u2); f4add(u4, u6); f4add(u0, u4);

            f4add(u0, f4shfl_down(u0, 16));
            f4add(u0, f4shfl_down(u0, 8));

            if (lane < 8) {
                const float inv = 1.0f / 1024.0f;
                u0.x *= inv; u0.y *= inv; u0.z *= inv; u0.w *= inv;
                out4[(size_t)b * F4_PER_BATCH + h * 8 + lane] = u0;
            }
        }
    } else {
        // ---- STORE block: zero batches 16..31 (rows 1+) -------------------
        const unsigned zid  = (unsigned)(bid - RED_BLOCKS);
        const unsigned step = ZERO_BLOCKS * (unsigned)NTHREADS;   // 86016
        for (unsigned i = F4_SPLIT + zid * (unsigned)NTHREADS + (unsigned)tid;
             i < N_F4_TOTAL; i += step) {
            if ((i & (F4_PER_BATCH - 1u)) >= F4_PER_ROW)   // skip row 0
                out4[i] = z;
        }
    }
}

extern "C" void kernel_launch(void* const* d_in, const int* in_sizes, int n_in,
                              void* d_out, int out_size) {
    const float4* x4 = (const float4*)d_in[0];   // user_embedding [32,1024,64]
    float4* out4 = (float4*)d_out;               // [32,1024,64]
    um_fused_kernel<<<TOTAL_BLOCKS, NTHREADS>>>(x4, out4);
}

// round 15
// speedup vs baseline: 1.3029x; 1.0337x over previous
#include <cuda_runtime.h>

// B=32, L=1024, D=64.
// Algebraic collapse (verified R1-R13, rel_err ~1.4e-7):
//   out[b,0,:] = sum_l x[b,l,:] / 1024 ;  out[b,1:,:] = 0.
//   W1,b1,W2,b2,timestamp are dead inputs.
//
// R14 = R6 structure (single kernel, grid 148 x 1024, 1 CTA/SM) with the
// store stream folded into the read blocks' load-latency window:
//   bids [0,64):   READ blocks (batch b, 128B half h). Issue 8 batched
//                  LDG.128, then 4 fire-and-forget STG.128 zeros (batches
//                  0..15, rows 1+) while loads are in flight, then reduce
//                  and exclusively write out[b,0,h*32 : h*32+32).
//   bids [64,148): STORE blocks: zero batches 16..31 rows 1+ (~3 STG/thread).
// All write sets disjoint; no atomics, no fences.

#define RED_BLOCKS   64
#define TOTAL_BLOCKS 148
#define ZERO_BLOCKS  (TOTAL_BLOCKS - RED_BLOCKS)
#define NTHREADS     1024

#define F4_PER_BATCH 16384u   // 1024 rows * 16 float4
#define F4_PER_ROW   16u
#define N_F4_TOTAL   (32u * F4_PER_BATCH)      // 524288
#define F4_SPLIT     (16u * F4_PER_BATCH)      // 262144: batches 0..15

__device__ __forceinline__ void f4add(float4& a, const float4& b) {
    a.x += b.x; a.y += b.y; a.z += b.z; a.w += b.w;
}

__device__ __forceinline__ float4 f4shfl_down(float4 v, int delta) {
    v.x = __shfl_down_sync(0xffffffffu, v.x, delta);
    v.y = __shfl_down_sync(0xffffffffu, v.y, delta);
    v.z = __shfl_down_sync(0xffffffffu, v.z, delta);
    v.w = __shfl_down_sync(0xffffffffu, v.w, delta);
    return v;
}

__global__ void __launch_bounds__(NTHREADS, 1) um_fused_kernel(
    const float4* __restrict__ x4, float4* __restrict__ out4)
{
    const int bid = blockIdx.x;
    const int tid = threadIdx.x;
    const float4 z = make_float4(0.f, 0.f, 0.f, 0.f);

    if (bid < RED_BLOCKS) {
        // ---- READ block: (b, h) owns the 128B slice h of row 0 -----------
        const int b  = bid >> 1;
        const int h  = bid & 1;
        const int c  = tid & 7;        // float4 column within 128B slice
        const int lg = tid >> 3;       // 0..127: row group

        const float4* base = x4 + (size_t)b * F4_PER_BATCH
                                + (size_t)lg * F4_PER_ROW + h * 8 + c;

        // 8 independent LDG.128 from one base + immediate offsets (MLP=8)
        float4 v[8];
        #pragma unroll
        for (int j = 0; j < 8; ++j)
            v[j] = base[(size_t)j * 128u * F4_PER_ROW];   // +128 rows each

        // while loads are in flight: 4 fire-and-forget zero stores
        // (batches 0..15, skipping each batch's row 0)
        {
            const unsigned gt = (unsigned)bid * NTHREADS + (unsigned)tid; // 0..65535
            #pragma unroll
            for (unsigned k = 0; k < 4; ++k) {
                unsigned i = gt + k * 65536u;   // < F4_SPLIT
                if ((i & (F4_PER_BATCH - 1u)) >= F4_PER_ROW)
                    out4[i] = z;
            }
        }

        float4 a0 = v[0], a1 = v[1], a2 = v[2], a3 = v[3];
        f4add(a0, v[4]); f4add(a1, v[5]); f4add(a2, v[6]); f4add(a3, v[7]);
        f4add(a0, a1); f4add(a2, a3); f4add(a0, a2);

        // warp reduce: lanes sharing (lane & 7) share a column
        f4add(a0, f4shfl_down(a0, 16));
        f4add(a0, f4shfl_down(a0, 8));

        __shared__ float4 sm[32][8];   // [warp][col]
        const int lane = tid & 31;
        const int wid  = tid >> 5;
        if (lane < 8) sm[wid][lane] = a0;
        __syncthreads();

        // single-warp batched final reduce
        if (wid == 0) {
            const int cc = lane & 7;
            const int g  = lane >> 3;
            float4 u0 = sm[g*8+0][cc], u1 = sm[g*8+1][cc];
            float4 u2 = sm[g*8+2][cc], u3 = sm[g*8+3][cc];
            float4 u4 = sm[g*8+4][cc], u5 = sm[g*8+5][cc];
            float4 u6 = sm[g*8+6][cc], u7 = sm[g*8+7][cc];
            f4add(u0, u1); f4add(u2, u3); f4add(u4, u5); f4add(u6, u7);
            f4add(u0, u2); f4add(u4, u6); f4add(u0, u4);

            f4add(u0, f4shfl_down(u0, 16));
            f4add(u0, f4shfl_down(u0, 8));

            if (lane < 8) {
                const float inv = 1.0f / 1024.0f;
                u0.x *= inv; u0.y *= inv; u0.z *= inv; u0.w *= inv;
                out4[(size_t)b * F4_PER_BATCH + h * 8 + lane] = u0;
            }
        }
    } else {
        // ---- STORE block: zero batches 16..31 (rows 1+) -------------------
        const unsigned zid  = (unsigned)(bid - RED_BLOCKS);
        const unsigned step = ZERO_BLOCKS * (unsigned)NTHREADS;   // 86016
        for (unsigned i = F4_SPLIT + zid * (unsigned)NTHREADS + (unsigned)tid;
             i < N_F4_TOTAL; i += step) {
            if ((i & (F4_PER_BATCH - 1u)) >= F4_PER_ROW)   // skip row 0
                out4[i] = z;
        }
    }
}

extern "C" void kernel_launch(void* const* d_in, const int* in_sizes, int n_in,
                              void* d_out, int out_size) {
    const float4* x4 = (const float4*)d_in[0];   // user_embedding [32,1024,64]
    float4* out4 = (float4*)d_out;               // [32,1024,64]
    um_fused_kernel<<<TOTAL_BLOCKS, NTHREADS>>>(x4, out4);
}